// round 1
// baseline (speedup 1.0000x reference)
#include <cuda_runtime.h>
#include <math.h>

#define BB 4
#define NTOK 4096
#define CC 256
#define BNTOK (BB * NTOK)   // 16384

// ---------------- static scratch (no allocs allowed) ----------------
__device__ float gQ [BNTOK * CC];
__device__ float gK [BNTOK * CC];
__device__ float gV [BNTOK * CC];
__device__ float gZ [BNTOK * CC];
__device__ float gPE[BNTOK * CC];
__device__ float gT [BNTOK * CC];
__device__ float gP [(size_t)BB * NTOK * NTOK];   // 256 MB attention matrix

// ---------------- epilogue modes ----------------
// 0: split qkv into gQ/gK/gV           (r = global row 0..16383, c 0..767)
// 1: z = gelu(acc + b_gate[c]) -> gZ
// 2: P = acc * SCALE -> gP             (batched, r,c in [0,4096))
// 3: T = (acc + PE) * Z -> gT          (batched)
// 4: final -> d_out

template<int TRANS_B, int MODE>
__global__ void __launch_bounds__(256)
gemm128(const float* __restrict__ A, const float* __restrict__ B,
        float* __restrict__ Out,
        int N, int K, int lda, int ldb,
        size_t sA, size_t sB,
        const float* __restrict__ bias)
{
    const int BK = 8;
    __shared__ float As[BK][128 + 4];
    __shared__ float Bs[BK][128 + 4];

    const int bz     = blockIdx.z;
    const float* Ab  = A + (size_t)bz * sA;
    const float* Bb  = B + (size_t)bz * sB;
    const int rowBlk = blockIdx.y * 128;
    const int colBlk = blockIdx.x * 128;
    const int tid    = threadIdx.x;
    const int tx     = tid & 15;
    const int ty     = tid >> 4;

    // A tile load mapping: 128 rows x 8 k, one float4 per thread along k
    const int a_row = tid >> 1;
    const int a_k   = (tid & 1) * 4;

    float acc[8][8];
    #pragma unroll
    for (int i = 0; i < 8; i++)
        #pragma unroll
        for (int j = 0; j < 8; j++) acc[i][j] = 0.0f;

    for (int kt = 0; kt < K; kt += BK) {
        float4 av = *(const float4*)(Ab + (size_t)(rowBlk + a_row) * lda + kt + a_k);
        As[a_k + 0][a_row] = av.x;
        As[a_k + 1][a_row] = av.y;
        As[a_k + 2][a_row] = av.z;
        As[a_k + 3][a_row] = av.w;

        if (TRANS_B) {
            // B is [N, K] row-major (K contiguous) — same pattern as A
            const int b_row = tid >> 1;
            const int b_k   = (tid & 1) * 4;
            float4 bv = *(const float4*)(Bb + (size_t)(colBlk + b_row) * ldb + kt + b_k);
            Bs[b_k + 0][b_row] = bv.x;
            Bs[b_k + 1][b_row] = bv.y;
            Bs[b_k + 2][b_row] = bv.z;
            Bs[b_k + 3][b_row] = bv.w;
        } else {
            // B is [K, N] row-major (N contiguous) — direct vector store
            const int b_k = tid >> 5;
            const int b_n = (tid & 31) * 4;
            float4 bv = *(const float4*)(Bb + (size_t)(kt + b_k) * ldb + colBlk + b_n);
            *(float4*)&Bs[b_k][b_n] = bv;
        }
        __syncthreads();

        #pragma unroll
        for (int k = 0; k < BK; k++) {
            float ar[8], br[8];
            *(float4*)(ar)     = *(const float4*)&As[k][ty * 8];
            *(float4*)(ar + 4) = *(const float4*)&As[k][ty * 8 + 4];
            *(float4*)(br)     = *(const float4*)&Bs[k][tx * 8];
            *(float4*)(br + 4) = *(const float4*)&Bs[k][tx * 8 + 4];
            #pragma unroll
            for (int i = 0; i < 8; i++)
                #pragma unroll
                for (int j = 0; j < 8; j++)
                    acc[i][j] = fmaf(ar[i], br[j], acc[i][j]);
        }
        __syncthreads();
    }

    #pragma unroll
    for (int i = 0; i < 8; i++) {
        const int r = rowBlk + ty * 8 + i;
        #pragma unroll
        for (int j = 0; j < 8; j++) {
            const int c = colBlk + tx * 8 + j;
            float v = acc[i][j];
            if (MODE == 0) {
                const size_t base = (size_t)r * CC;
                if (c < 256)      gQ[base + c]       = v;
                else if (c < 512) gK[base + c - 256] = v;
                else              gV[base + c - 512] = v;
            } else if (MODE == 1) {
                v += bias[c];
                gZ[(size_t)r * CC + c] = 0.5f * v * (1.0f + erff(v * 0.70710678118654752f));
            } else if (MODE == 2) {
                gP[(size_t)bz * NTOK * NTOK + (size_t)r * NTOK + c] = v * 0.0625f;
            } else if (MODE == 3) {
                const size_t idx = ((size_t)bz * NTOK + r) * CC + c;
                gT[idx] = (v + gPE[idx]) * gZ[idx];
            } else {
                Out[(size_t)r * CC + c] = v;
            }
        }
    }
}

// ---------------- row softmax over P (rows of length 4096) ----------------
__global__ void __launch_bounds__(256)
softmax_rows(float* __restrict__ P)
{
    float* row = P + (size_t)blockIdx.x * NTOK;
    const int tid = threadIdx.x;
    __shared__ float red[256];

    float m = -3.4e38f;
    #pragma unroll 4
    for (int i = tid; i < NTOK; i += 256) m = fmaxf(m, row[i]);
    red[tid] = m; __syncthreads();
    for (int s = 128; s > 0; s >>= 1) {
        if (tid < s) red[tid] = fmaxf(red[tid], red[tid + s]);
        __syncthreads();
    }
    m = red[0]; __syncthreads();

    float sum = 0.0f;
    #pragma unroll 4
    for (int i = tid; i < NTOK; i += 256) {
        float e = __expf(row[i] - m);
        row[i] = e;
        sum += e;
    }
    red[tid] = sum; __syncthreads();
    for (int s = 128; s > 0; s >>= 1) {
        if (tid < s) red[tid] += red[tid + s];
        __syncthreads();
    }
    const float inv = 1.0f / red[0];
    #pragma unroll 4
    for (int i = tid; i < NTOK; i += 256) row[i] *= inv;
}

// ---------------- depthwise 3x3 conv on q (image 64x64, zero-pad SAME) ----
__global__ void __launch_bounds__(256)
dwconv_pe(const float* __restrict__ w, const float* __restrict__ bias)
{
    const int idx = blockIdx.x * 256 + threadIdx.x;  // over BB*NTOK*CC
    const int c = idx & 255;
    const int n = (idx >> 8) & (NTOK - 1);
    const int b = idx >> 20;
    const int h = n >> 6;
    const int wd = n & 63;

    const float* q = gQ + (size_t)b * NTOK * CC;
    float acc = bias[c];
    #pragma unroll
    for (int di = -1; di <= 1; di++) {
        const int hh = h + di;
        if (hh < 0 || hh > 63) continue;
        #pragma unroll
        for (int dj = -1; dj <= 1; dj++) {
            const int w2 = wd + dj;
            if (w2 < 0 || w2 > 63) continue;
            acc = fmaf(q[(size_t)(hh * 64 + w2) * CC + c],
                       w[c * 9 + (di + 1) * 3 + (dj + 1)], acc);
        }
    }
    gPE[idx] = acc;
}

// ---------------- launch ----------------
extern "C" void kernel_launch(void* const* d_in, const int* in_sizes, int n_in,
                              void* d_out, int out_size)
{
    const float* x     = (const float*)d_in[0];
    const float* Wqkv  = (const float*)d_in[1];
    const float* Wgate = (const float*)d_in[2];
    const float* bgate = (const float*)d_in[3];
    const float* Wproj = (const float*)d_in[4];
    const float* pew   = (const float*)d_in[5];
    const float* peb   = (const float*)d_in[6];
    float* out = (float*)d_out;

    float *pQ, *pK, *pV, *pP, *pT;
    cudaGetSymbolAddress((void**)&pQ, gQ);
    cudaGetSymbolAddress((void**)&pK, gK);
    cudaGetSymbolAddress((void**)&pV, gV);
    cudaGetSymbolAddress((void**)&pP, gP);
    cudaGetSymbolAddress((void**)&pT, gT);

    dim3 blk(256);

    // 1) qkv = x @ W_qkv : [16384,256]x[256,768]
    gemm128<0, 0><<<dim3(6, 128, 1), blk>>>(x, Wqkv, nullptr, 768, 256, 256, 768, 0, 0, nullptr);

    // 2) z = gelu(x @ W_gate + b) : [16384,256]x[256,256]
    gemm128<0, 1><<<dim3(2, 128, 1), blk>>>(x, Wgate, nullptr, 256, 256, 256, 256, 0, 0, bgate);

    // 3) depthwise-conv PE from q
    dwconv_pe<<<dim3(BNTOK * CC / 256), blk>>>(pew, peb);

    // 4) P = (Q K^T) * SCALE, batched over 4
    gemm128<1, 2><<<dim3(32, 32, BB), blk>>>(pQ, pK, nullptr, NTOK, CC, CC, CC,
                                             (size_t)NTOK * CC, (size_t)NTOK * CC, nullptr);

    // 5) row softmax, 16384 rows
    softmax_rows<<<dim3(BB * NTOK), blk>>>(pP);

    // 6) T = (P @ V + PE) * Z, batched
    gemm128<0, 3><<<dim3(2, 32, BB), blk>>>(pP, pV, nullptr, CC, NTOK, NTOK, CC,
                                            (size_t)NTOK * NTOK, (size_t)NTOK * CC, nullptr);

    // 7) out = T @ W_proj
    gemm128<0, 4><<<dim3(2, 128, 1), blk>>>(pT, Wproj, out, CC, CC, CC, CC, 0, 0, nullptr);
}

// round 3
// speedup vs baseline: 2.8065x; 2.8065x over previous
#include <cuda_runtime.h>
#include <math.h>
#include <stdint.h>

#define BB 4
#define NTOK 4096
#define CC 256
#define BNTOK (BB * NTOK)   // 16384

// ---------------- static scratch ----------------
__device__ float gQ [(size_t)BNTOK * CC];
__device__ float gK [(size_t)BNTOK * CC];
__device__ float gV [(size_t)BNTOK * CC];
__device__ float gZ [(size_t)BNTOK * CC];
__device__ float gPE[(size_t)BNTOK * CC];
__device__ float gT [(size_t)BNTOK * CC];
__device__ float gP [(size_t)BB * NTOK * NTOK];   // 256 MB

__device__ __forceinline__ uint32_t f2tf32(float f) {
    uint32_t u;
    asm("cvt.rna.tf32.f32 %0, %1;" : "=r"(u) : "f"(f));
    return u;
}

__device__ __forceinline__ void mma_tf32(float d[4], uint32_t a0, uint32_t a1,
                                         uint32_t a2, uint32_t a3,
                                         uint32_t b0, uint32_t b1) {
    asm volatile(
        "mma.sync.aligned.m16n8k8.row.col.f32.tf32.tf32.f32 "
        "{%0,%1,%2,%3}, {%4,%5,%6,%7}, {%8,%9}, {%0,%1,%2,%3};"
        : "+f"(d[0]), "+f"(d[1]), "+f"(d[2]), "+f"(d[3])
        : "r"(a0), "r"(a1), "r"(a2), "r"(a3), "r"(b0), "r"(b1));
}

// ---------------- tensor-core tf32 GEMM ----------------
// D[m][n] = sum_k A[m][k] * Bop[n][k]
// TRB=1: B stored [N,K] row-major (K contiguous)  -> direct tiles
// TRB=0: B stored [K,N] row-major (N contiguous)  -> transpose path
// Block tile 128x128, BK=32, 8 warps (2x4), warp tile 64x32.
// MODE 0: qkv split -> gQ/gK/gV
// MODE 1: gZ = gelu(acc + bias)
// MODE 2: gP = acc * 0.0625
// MODE 3: gT = (acc + gPE) * gZ  (batched)
// MODE 4: Out = acc

#define ASTR 36     // floats per A/B-direct smem row (128 rows x 36)
#define BSTR 136    // floats per B-transpose smem row (32 rows x 136)
#define AFL  (128 * ASTR)          // 4608 floats
#define BFL1 (128 * ASTR)          // 4608
#define BFL0 (32 * BSTR)           // 4352

template<int MODE, int TRB>
__global__ void __launch_bounds__(256, 1)
mmagemm(const float* __restrict__ A, const float* __restrict__ B, float* __restrict__ Out,
        int K, int lda, int ldb, size_t sA, size_t sB, const float* __restrict__ bias)
{
    extern __shared__ __align__(16) float sm[];
    constexpr int BFL = TRB ? BFL1 : BFL0;
    uint32_t* As = (uint32_t*)sm;                    // 2 buffers of AFL
    uint32_t* Bs = (uint32_t*)(sm + 2 * AFL);        // 2 buffers of BFL

    const int tid  = threadIdx.x;
    const int wid  = tid >> 5;
    const int lane = tid & 31;
    const int g    = lane >> 2;      // 0..7
    const int t    = lane & 3;       // 0..3
    const int wm   = wid >> 2;       // 0..1
    const int wn   = wid & 3;        // 0..3

    const int bz     = blockIdx.z;
    const int rowBlk = blockIdx.y * 128;
    const int colBlk = blockIdx.x * 128;
    const float* Ab = A + (size_t)bz * sA;
    const float* Bb = B + (size_t)bz * sB;

    float d[4][4][4];
    #pragma unroll
    for (int mi = 0; mi < 4; mi++)
        #pragma unroll
        for (int ni = 0; ni < 4; ni++)
            #pragma unroll
            for (int j = 0; j < 4; j++) d[mi][ni][j] = 0.0f;

    // ---- global load mappings ----
    const int a_row = tid >> 3;          // 0..31 (x4 rows via i)
    const int a_kq  = tid & 7;           // float4 along K
    const int b0_k  = tid >> 5;          // TRB0: k row (x4 via i)
    const int b0_n4 = tid & 31;          // TRB0: float4 along N
    const int NC = K >> 5;

    float4 aR[4], bR[4];

    // prologue: load chunk 0
    #pragma unroll
    for (int i = 0; i < 4; i++)
        aR[i] = *(const float4*)(Ab + (size_t)(rowBlk + a_row + 32 * i) * lda + a_kq * 4);
    if (TRB) {
        #pragma unroll
        for (int i = 0; i < 4; i++)
            bR[i] = *(const float4*)(Bb + (size_t)(colBlk + a_row + 32 * i) * ldb + a_kq * 4);
    } else {
        #pragma unroll
        for (int i = 0; i < 4; i++)
            bR[i] = *(const float4*)(Bb + (size_t)(b0_k + 8 * i) * ldb + colBlk + b0_n4 * 4);
    }

    for (int c = 0; c < NC; ++c) {
        const int buf = c & 1;
        uint32_t* Ab_s = As + buf * AFL;
        uint32_t* Bb_s = Bs + buf * BFL;

        // ---- STS current chunk (with tf32 rounding) ----
        #pragma unroll
        for (int i = 0; i < 4; i++) {
            uint32_t* p = Ab_s + (a_row + 32 * i) * ASTR + a_kq * 4;
            p[0] = f2tf32(aR[i].x); p[1] = f2tf32(aR[i].y);
            p[2] = f2tf32(aR[i].z); p[3] = f2tf32(aR[i].w);
        }
        if (TRB) {
            #pragma unroll
            for (int i = 0; i < 4; i++) {
                uint32_t* p = Bb_s + (a_row + 32 * i) * ASTR + a_kq * 4;
                p[0] = f2tf32(bR[i].x); p[1] = f2tf32(bR[i].y);
                p[2] = f2tf32(bR[i].z); p[3] = f2tf32(bR[i].w);
            }
        } else {
            #pragma unroll
            for (int i = 0; i < 4; i++) {
                uint32_t* p = Bb_s + (b0_k + 8 * i) * BSTR + b0_n4 * 4;
                p[0] = f2tf32(bR[i].x); p[1] = f2tf32(bR[i].y);
                p[2] = f2tf32(bR[i].z); p[3] = f2tf32(bR[i].w);
            }
        }
        __syncthreads();

        // ---- prefetch next chunk to regs ----
        if (c + 1 < NC) {
            const int kt = (c + 1) << 5;
            #pragma unroll
            for (int i = 0; i < 4; i++)
                aR[i] = *(const float4*)(Ab + (size_t)(rowBlk + a_row + 32 * i) * lda + kt + a_kq * 4);
            if (TRB) {
                #pragma unroll
                for (int i = 0; i < 4; i++)
                    bR[i] = *(const float4*)(Bb + (size_t)(colBlk + a_row + 32 * i) * ldb + kt + a_kq * 4);
            } else {
                #pragma unroll
                for (int i = 0; i < 4; i++)
                    bR[i] = *(const float4*)(Bb + (size_t)(kt + b0_k + 8 * i) * ldb + colBlk + b0_n4 * 4);
            }
        }

        // ---- compute 4 k-steps ----
        #pragma unroll
        for (int s = 0; s < 4; s++) {
            const int k0 = 8 * s;
            uint32_t af[4][4];
            #pragma unroll
            for (int mi = 0; mi < 4; mi++) {
                const int row = wm * 64 + mi * 16;
                af[mi][0] = Ab_s[(row + g) * ASTR + k0 + t];
                af[mi][1] = Ab_s[(row + 8 + g) * ASTR + k0 + t];
                af[mi][2] = Ab_s[(row + g) * ASTR + k0 + t + 4];
                af[mi][3] = Ab_s[(row + 8 + g) * ASTR + k0 + t + 4];
            }
            uint32_t bf[4][2];
            #pragma unroll
            for (int ni = 0; ni < 4; ni++) {
                const int nb = wn * 32 + ni * 8 + g;
                if (TRB) {
                    bf[ni][0] = Bb_s[nb * ASTR + k0 + t];
                    bf[ni][1] = Bb_s[nb * ASTR + k0 + t + 4];
                } else {
                    bf[ni][0] = Bb_s[(k0 + t) * BSTR + nb];
                    bf[ni][1] = Bb_s[(k0 + t + 4) * BSTR + nb];
                }
            }
            #pragma unroll
            for (int mi = 0; mi < 4; mi++)
                #pragma unroll
                for (int ni = 0; ni < 4; ni++)
                    mma_tf32(d[mi][ni], af[mi][0], af[mi][1], af[mi][2], af[mi][3],
                             bf[ni][0], bf[ni][1]);
        }
        __syncthreads();
    }

    // ---- epilogue ----
    #pragma unroll
    for (int mi = 0; mi < 4; mi++) {
        #pragma unroll
        for (int half = 0; half < 2; half++) {
            const int r = rowBlk + wm * 64 + mi * 16 + g + half * 8;
            #pragma unroll
            for (int ni = 0; ni < 4; ni++) {
                const int c = colBlk + wn * 32 + ni * 8 + 2 * t;
                float v0 = d[mi][ni][2 * half + 0];
                float v1 = d[mi][ni][2 * half + 1];

                if (MODE == 2) {
                    float2 v = make_float2(v0 * 0.0625f, v1 * 0.0625f);
                    *(float2*)&gP[(size_t)bz * NTOK * NTOK + (size_t)r * NTOK + c] = v;
                } else if (MODE == 3) {
                    const size_t idx = ((size_t)(bz * NTOK + r)) * CC + c;
                    float2 pe = *(const float2*)&gPE[idx];
                    float2 zz = *(const float2*)&gZ[idx];
                    float2 v = make_float2((v0 + pe.x) * zz.x, (v1 + pe.y) * zz.y);
                    *(float2*)&gT[idx] = v;
                } else if (MODE == 0) {
                    const int seg = c >> 8;
                    const int cc = c & 255;
                    float* dst = (seg == 0) ? gQ : (seg == 1) ? gK : gV;
                    *(float2*)&dst[(size_t)r * CC + cc] = make_float2(v0, v1);
                } else if (MODE == 1) {
                    float2 bb = *(const float2*)&bias[c];
                    float a0 = v0 + bb.x, a1 = v1 + bb.y;
                    float2 v;
                    v.x = 0.5f * a0 * (1.0f + erff(a0 * 0.70710678118654752f));
                    v.y = 0.5f * a1 * (1.0f + erff(a1 * 0.70710678118654752f));
                    *(float2*)&gZ[(size_t)r * CC + c] = v;
                } else {
                    *(float2*)&Out[(size_t)r * CC + c] = make_float2(v0, v1);
                }
            }
        }
    }
}

// ---------------- single-pass row softmax ----------------
__global__ void __launch_bounds__(256)
softmax_rows(float* __restrict__ P)
{
    float4* row = reinterpret_cast<float4*>(P + (size_t)blockIdx.x * NTOK);
    const int tid = threadIdx.x;
    __shared__ float red[256];

    float4 v[4];
    #pragma unroll
    for (int j = 0; j < 4; j++) v[j] = row[tid + j * 256];

    float m = -3.4e38f;
    #pragma unroll
    for (int j = 0; j < 4; j++)
        m = fmaxf(m, fmaxf(fmaxf(v[j].x, v[j].y), fmaxf(v[j].z, v[j].w)));
    red[tid] = m; __syncthreads();
    for (int s = 128; s > 0; s >>= 1) {
        if (tid < s) red[tid] = fmaxf(red[tid], red[tid + s]);
        __syncthreads();
    }
    m = red[0]; __syncthreads();

    float sum = 0.0f;
    #pragma unroll
    for (int j = 0; j < 4; j++) {
        v[j].x = __expf(v[j].x - m); v[j].y = __expf(v[j].y - m);
        v[j].z = __expf(v[j].z - m); v[j].w = __expf(v[j].w - m);
        sum += v[j].x + v[j].y + v[j].z + v[j].w;
    }
    red[tid] = sum; __syncthreads();
    for (int s = 128; s > 0; s >>= 1) {
        if (tid < s) red[tid] += red[tid + s];
        __syncthreads();
    }
    const float inv = 1.0f / red[0];
    #pragma unroll
    for (int j = 0; j < 4; j++) {
        v[j].x *= inv; v[j].y *= inv; v[j].z *= inv; v[j].w *= inv;
        row[tid + j * 256] = v[j];
    }
}

// ---------------- depthwise 3x3 conv PE on q ----------------
__global__ void __launch_bounds__(256)
dwconv_pe(const float* __restrict__ w, const float* __restrict__ bias)
{
    const int idx = blockIdx.x * 256 + threadIdx.x;
    const int c = idx & 255;
    const int n = (idx >> 8) & (NTOK - 1);
    const int b = idx >> 20;
    const int h = n >> 6;
    const int wd = n & 63;

    const float* q = gQ + (size_t)b * NTOK * CC;
    float acc = bias[c];
    #pragma unroll
    for (int di = -1; di <= 1; di++) {
        const int hh = h + di;
        if (hh < 0 || hh > 63) continue;
        #pragma unroll
        for (int dj = -1; dj <= 1; dj++) {
            const int w2 = wd + dj;
            if (w2 < 0 || w2 > 63) continue;
            acc = fmaf(q[(size_t)(hh * 64 + w2) * CC + c],
                       w[c * 9 + (di + 1) * 3 + (dj + 1)], acc);
        }
    }
    gPE[idx] = acc;
}

// ---------------- launch ----------------
extern "C" void kernel_launch(void* const* d_in, const int* in_sizes, int n_in,
                              void* d_out, int out_size)
{
    const float* x     = (const float*)d_in[0];
    const float* Wqkv  = (const float*)d_in[1];
    const float* Wgate = (const float*)d_in[2];
    const float* bgate = (const float*)d_in[3];
    const float* Wproj = (const float*)d_in[4];
    const float* pew   = (const float*)d_in[5];
    const float* peb   = (const float*)d_in[6];
    float* out = (float*)d_out;

    float *pQ, *pK, *pV, *pP, *pT;
    cudaGetSymbolAddress((void**)&pQ, gQ);
    cudaGetSymbolAddress((void**)&pK, gK);
    cudaGetSymbolAddress((void**)&pV, gV);
    cudaGetSymbolAddress((void**)&pP, gP);
    cudaGetSymbolAddress((void**)&pT, gT);

    constexpr int SM0 = (2 * AFL + 2 * BFL0) * 4;   // 71680 (transpose-B)
    constexpr int SM1 = (2 * AFL + 2 * BFL1) * 4;   // 73728 (direct-B)
    cudaFuncSetAttribute(mmagemm<0,0>, cudaFuncAttributeMaxDynamicSharedMemorySize, SM0);
    cudaFuncSetAttribute(mmagemm<1,0>, cudaFuncAttributeMaxDynamicSharedMemorySize, SM0);
    cudaFuncSetAttribute(mmagemm<2,1>, cudaFuncAttributeMaxDynamicSharedMemorySize, SM1);
    cudaFuncSetAttribute(mmagemm<3,0>, cudaFuncAttributeMaxDynamicSharedMemorySize, SM0);
    cudaFuncSetAttribute(mmagemm<4,0>, cudaFuncAttributeMaxDynamicSharedMemorySize, SM0);

    // 1) qkv = x @ W_qkv  (B=[256,768] K,N layout -> transpose path)
    mmagemm<0,0><<<dim3(6,128,1), 256, SM0>>>(x, Wqkv, nullptr, 256, 256, 768, 0, 0, nullptr);
    // 2) z = gelu(x @ W_gate + b)
    mmagemm<1,0><<<dim3(2,128,1), 256, SM0>>>(x, Wgate, nullptr, 256, 256, 256, 0, 0, bgate);
    // 3) PE depthwise conv from gQ
    dwconv_pe<<<dim3(BNTOK * CC / 256), 256>>>(pew, peb);
    // 4) P = scale * Q K^T (batched; B=K matrix [N,K] -> direct)
    mmagemm<2,1><<<dim3(32,32,BB), 256, SM1>>>(pQ, pK, nullptr, 256, 256, 256,
                                               (size_t)NTOK * CC, (size_t)NTOK * CC, nullptr);
    // 5) softmax rows
    softmax_rows<<<dim3(BB * NTOK), 256>>>(pP);
    // 6) T = (P @ V + PE) * Z  (B=V [K,N] -> transpose path)
    mmagemm<3,0><<<dim3(2,32,BB), 256, SM0>>>(pP, pV, nullptr, 4096, 4096, 256,
                                              (size_t)NTOK * NTOK, (size_t)NTOK * CC, nullptr);
    // 7) out = T @ W_proj
    mmagemm<4,0><<<dim3(2,128,1), 256, SM0>>>(pT, Wproj, out, 256, 256, 256, 0, 0, nullptr);
}

// round 4
// speedup vs baseline: 3.1874x; 1.1357x over previous
#include <cuda_runtime.h>
#include <math.h>
#include <stdint.h>

#define BB 4
#define NTOK 4096
#define CC 256
#define BNTOK (BB * NTOK)   // 16384

// ---------------- static scratch ----------------
__device__ float gQ [(size_t)BNTOK * CC];
__device__ float gK [(size_t)BNTOK * CC];
__device__ float gV [(size_t)BNTOK * CC];
__device__ float gZ [(size_t)BNTOK * CC];
__device__ float gPE[(size_t)BNTOK * CC];
__device__ float gT [(size_t)BNTOK * CC];
__device__ float gP [(size_t)BB * NTOK * NTOK];   // 256 MB

__device__ __forceinline__ uint32_t f2tf32(float f) {
    uint32_t u;
    asm("cvt.rna.tf32.f32 %0, %1;" : "=r"(u) : "f"(f));
    return u;
}
__device__ __forceinline__ float f2tf32f(float f) {
    return __uint_as_float(f2tf32(f));
}

__device__ __forceinline__ void mma_tf32(float d[4], uint32_t a0, uint32_t a1,
                                         uint32_t a2, uint32_t a3,
                                         uint32_t b0, uint32_t b1) {
    asm volatile(
        "mma.sync.aligned.m16n8k8.row.col.f32.tf32.tf32.f32 "
        "{%0,%1,%2,%3}, {%4,%5,%6,%7}, {%8,%9}, {%0,%1,%2,%3};"
        : "+f"(d[0]), "+f"(d[1]), "+f"(d[2]), "+f"(d[3])
        : "r"(a0), "r"(a1), "r"(a2), "r"(a3), "r"(b0), "r"(b1));
}

__device__ __forceinline__ void cpa16(uint32_t dst, const void* src) {
    asm volatile("cp.async.ca.shared.global [%0], [%1], 16;" :: "r"(dst), "l"(src));
}

#define ASTR 36     // floats per A/B-direct smem row
#define BSTR 136    // floats per B-transpose smem row (32 k-rows x 128n + pad)
#define BFL1 (128 * ASTR)          // direct-B floats per stage
#define BFL0 (32 * BSTR)           // trans-B floats per stage

// ======================================================================
// Sync GEMM (register prefetch + tf32 cvt at STS) — for small GEMMs.
// D[m][n] = sum_k A[m][k]*Bop[n][k];  TRB=1: B [N,K]; TRB=0: B [K,N].
// MODE 0: qkv split -> gQ/gK/gV (tf32-rounded)
// MODE 1: gZ = gelu(acc+bias)
// MODE 4: Out = acc
// ======================================================================
#define AFL  (128 * ASTR)

template<int MODE, int TRB>
__global__ void __launch_bounds__(256, 1)
mmagemm(const float* __restrict__ A, const float* __restrict__ B, float* __restrict__ Out,
        int K, int lda, int ldb, size_t sA, size_t sB, const float* __restrict__ bias)
{
    extern __shared__ __align__(16) float sm[];
    constexpr int BFL = TRB ? BFL1 : BFL0;
    uint32_t* As = (uint32_t*)sm;
    uint32_t* Bs = (uint32_t*)(sm + 2 * AFL);

    const int tid  = threadIdx.x;
    const int wid  = tid >> 5;
    const int lane = tid & 31;
    const int g    = lane >> 2;
    const int t    = lane & 3;
    const int wm   = wid >> 2;
    const int wn   = wid & 3;

    const int bz     = blockIdx.z;
    const int rowBlk = blockIdx.y * 128;
    const int colBlk = blockIdx.x * 128;
    const float* Ab = A + (size_t)bz * sA;
    const float* Bb = B + (size_t)bz * sB;

    float d[4][4][4];
    #pragma unroll
    for (int mi = 0; mi < 4; mi++)
        #pragma unroll
        for (int ni = 0; ni < 4; ni++)
            #pragma unroll
            for (int j = 0; j < 4; j++) d[mi][ni][j] = 0.0f;

    const int a_row = tid >> 3;
    const int a_kq  = tid & 7;
    const int b0_k  = tid >> 5;
    const int b0_n4 = tid & 31;
    const int NC = K >> 5;

    float4 aR[4], bR[4];
    #pragma unroll
    for (int i = 0; i < 4; i++)
        aR[i] = *(const float4*)(Ab + (size_t)(rowBlk + a_row + 32 * i) * lda + a_kq * 4);
    if (TRB) {
        #pragma unroll
        for (int i = 0; i < 4; i++)
            bR[i] = *(const float4*)(Bb + (size_t)(colBlk + a_row + 32 * i) * ldb + a_kq * 4);
    } else {
        #pragma unroll
        for (int i = 0; i < 4; i++)
            bR[i] = *(const float4*)(Bb + (size_t)(b0_k + 8 * i) * ldb + colBlk + b0_n4 * 4);
    }

    for (int c = 0; c < NC; ++c) {
        const int buf = c & 1;
        uint32_t* Ab_s = As + buf * AFL;
        uint32_t* Bb_s = Bs + buf * BFL;

        #pragma unroll
        for (int i = 0; i < 4; i++) {
            uint32_t* p = Ab_s + (a_row + 32 * i) * ASTR + a_kq * 4;
            p[0] = f2tf32(aR[i].x); p[1] = f2tf32(aR[i].y);
            p[2] = f2tf32(aR[i].z); p[3] = f2tf32(aR[i].w);
        }
        if (TRB) {
            #pragma unroll
            for (int i = 0; i < 4; i++) {
                uint32_t* p = Bb_s + (a_row + 32 * i) * ASTR + a_kq * 4;
                p[0] = f2tf32(bR[i].x); p[1] = f2tf32(bR[i].y);
                p[2] = f2tf32(bR[i].z); p[3] = f2tf32(bR[i].w);
            }
        } else {
            #pragma unroll
            for (int i = 0; i < 4; i++) {
                uint32_t* p = Bb_s + (b0_k + 8 * i) * BSTR + b0_n4 * 4;
                p[0] = f2tf32(bR[i].x); p[1] = f2tf32(bR[i].y);
                p[2] = f2tf32(bR[i].z); p[3] = f2tf32(bR[i].w);
            }
        }
        __syncthreads();

        if (c + 1 < NC) {
            const int kt = (c + 1) << 5;
            #pragma unroll
            for (int i = 0; i < 4; i++)
                aR[i] = *(const float4*)(Ab + (size_t)(rowBlk + a_row + 32 * i) * lda + kt + a_kq * 4);
            if (TRB) {
                #pragma unroll
                for (int i = 0; i < 4; i++)
                    bR[i] = *(const float4*)(Bb + (size_t)(colBlk + a_row + 32 * i) * ldb + kt + a_kq * 4);
            } else {
                #pragma unroll
                for (int i = 0; i < 4; i++)
                    bR[i] = *(const float4*)(Bb + (size_t)(kt + b0_k + 8 * i) * ldb + colBlk + b0_n4 * 4);
            }
        }

        #pragma unroll
        for (int s = 0; s < 4; s++) {
            const int k0 = 8 * s;
            uint32_t af[4][4];
            #pragma unroll
            for (int mi = 0; mi < 4; mi++) {
                const int row = wm * 64 + mi * 16;
                af[mi][0] = Ab_s[(row + g) * ASTR + k0 + t];
                af[mi][1] = Ab_s[(row + 8 + g) * ASTR + k0 + t];
                af[mi][2] = Ab_s[(row + g) * ASTR + k0 + t + 4];
                af[mi][3] = Ab_s[(row + 8 + g) * ASTR + k0 + t + 4];
            }
            uint32_t bf[4][2];
            #pragma unroll
            for (int ni = 0; ni < 4; ni++) {
                const int nb = wn * 32 + ni * 8 + g;
                if (TRB) {
                    bf[ni][0] = Bb_s[nb * ASTR + k0 + t];
                    bf[ni][1] = Bb_s[nb * ASTR + k0 + t + 4];
                } else {
                    bf[ni][0] = Bb_s[(k0 + t) * BSTR + nb];
                    bf[ni][1] = Bb_s[(k0 + t + 4) * BSTR + nb];
                }
            }
            #pragma unroll
            for (int mi = 0; mi < 4; mi++)
                #pragma unroll
                for (int ni = 0; ni < 4; ni++)
                    mma_tf32(d[mi][ni], af[mi][0], af[mi][1], af[mi][2], af[mi][3],
                             bf[ni][0], bf[ni][1]);
        }
        __syncthreads();
    }

    #pragma unroll
    for (int mi = 0; mi < 4; mi++) {
        #pragma unroll
        for (int half = 0; half < 2; half++) {
            const int r = rowBlk + wm * 64 + mi * 16 + g + half * 8;
            #pragma unroll
            for (int ni = 0; ni < 4; ni++) {
                const int c = colBlk + wn * 32 + ni * 8 + 2 * t;
                float v0 = d[mi][ni][2 * half + 0];
                float v1 = d[mi][ni][2 * half + 1];

                if (MODE == 0) {
                    const int seg = c >> 8;
                    const int cc = c & 255;
                    float* dst = (seg == 0) ? gQ : (seg == 1) ? gK : gV;
                    *(float2*)&dst[(size_t)r * CC + cc] =
                        make_float2(f2tf32f(v0), f2tf32f(v1));
                } else if (MODE == 1) {
                    float2 bb = *(const float2*)&bias[c];
                    float a0 = v0 + bb.x, a1 = v1 + bb.y;
                    float2 v;
                    v.x = 0.5f * a0 * (1.0f + erff(a0 * 0.70710678118654752f));
                    v.y = 0.5f * a1 * (1.0f + erff(a1 * 0.70710678118654752f));
                    *(float2*)&gZ[(size_t)r * CC + c] = v;
                } else {
                    *(float2*)&Out[(size_t)r * CC + c] = make_float2(v0, v1);
                }
            }
        }
    }
}

// ======================================================================
// Async GEMM: cp.async 3-stage pipeline, pre-rounded tf32 inputs.
// MI=4 -> 128-row tile; MI=2 -> 64-row tile. N tile fixed 128.
// MODE 2: gP = acc * 0.0625     MODE 3: gT = (acc + gPE) * gZ
// ======================================================================
template<int MODE, int TRB, int MI>
__global__ void __launch_bounds__(256, 2)
mmagemm_async(const float* __restrict__ A, const float* __restrict__ B,
              int K, int lda, int ldb, size_t sA, size_t sB)
{
    extern __shared__ __align__(16) float sm[];
    constexpr int S = 3;
    constexpr int AFLm = MI * 32 * ASTR;                 // floats per A stage
    constexpr int BFL  = TRB ? BFL1 : BFL0;
    const uint32_t smb = (uint32_t)__cvta_generic_to_shared(sm);
    const uint32_t aBase = smb;
    const uint32_t bBase = smb + S * AFLm * 4;

    const int tid  = threadIdx.x;
    const int wid  = tid >> 5;
    const int lane = tid & 31;
    const int g    = lane >> 2;
    const int t    = lane & 3;
    const int wm   = wid >> 2;
    const int wn   = wid & 3;

    const int bz     = blockIdx.z;
    const int rowBlk = blockIdx.y * (MI * 32);
    const int colBlk = blockIdx.x * 128;
    const float* Ab = A + (size_t)bz * sA;
    const float* Bb = B + (size_t)bz * sB;

    const int a_row = tid >> 3;
    const int a_kq  = tid & 7;
    const int b0_k  = tid >> 5;
    const int b0_n4 = tid & 31;
    const int NC = K >> 5;

    float d[MI][4][4];
    #pragma unroll
    for (int mi = 0; mi < MI; mi++)
        #pragma unroll
        for (int ni = 0; ni < 4; ni++)
            #pragma unroll
            for (int j = 0; j < 4; j++) d[mi][ni][j] = 0.0f;

    auto loadStage = [&](int c) {
        const int kt = c << 5;
        const int sb = c % S;
        const uint32_t aS = aBase + sb * AFLm * 4;
        #pragma unroll
        for (int i = 0; i < MI; i++)
            cpa16(aS + ((a_row + 32 * i) * ASTR + a_kq * 4) * 4,
                  Ab + (size_t)(rowBlk + a_row + 32 * i) * lda + kt + a_kq * 4);
        const uint32_t bS = bBase + sb * BFL * 4;
        if (TRB) {
            #pragma unroll
            for (int i = 0; i < 4; i++)
                cpa16(bS + ((a_row + 32 * i) * ASTR + a_kq * 4) * 4,
                      Bb + (size_t)(colBlk + a_row + 32 * i) * ldb + kt + a_kq * 4);
        } else {
            #pragma unroll
            for (int i = 0; i < 4; i++)
                cpa16(bS + ((b0_k + 8 * i) * BSTR + b0_n4 * 4) * 4,
                      Bb + (size_t)(kt + b0_k + 8 * i) * ldb + colBlk + b0_n4 * 4);
        }
        asm volatile("cp.async.commit_group;");
    };

    loadStage(0);
    loadStage(1);

    for (int c = 0; c < NC; ++c) {
        asm volatile("cp.async.wait_group 1;");
        __syncthreads();
        if (c + S - 1 < NC) loadStage(c + S - 1);

        const int sb = c % S;
        const uint32_t* Ab_s = (const uint32_t*)(sm + sb * AFLm);
        const uint32_t* Bb_s = (const uint32_t*)(sm + S * AFLm + sb * BFL);

        #pragma unroll
        for (int s = 0; s < 4; s++) {
            const int k0 = 8 * s;
            uint32_t af[MI][4];
            #pragma unroll
            for (int mi = 0; mi < MI; mi++) {
                const int row = wm * (MI * 16) + mi * 16;
                af[mi][0] = Ab_s[(row + g) * ASTR + k0 + t];
                af[mi][1] = Ab_s[(row + 8 + g) * ASTR + k0 + t];
                af[mi][2] = Ab_s[(row + g) * ASTR + k0 + t + 4];
                af[mi][3] = Ab_s[(row + 8 + g) * ASTR + k0 + t + 4];
            }
            uint32_t bf[4][2];
            #pragma unroll
            for (int ni = 0; ni < 4; ni++) {
                const int nb = wn * 32 + ni * 8 + g;
                if (TRB) {
                    bf[ni][0] = Bb_s[nb * ASTR + k0 + t];
                    bf[ni][1] = Bb_s[nb * ASTR + k0 + t + 4];
                } else {
                    bf[ni][0] = Bb_s[(k0 + t) * BSTR + nb];
                    bf[ni][1] = Bb_s[(k0 + t + 4) * BSTR + nb];
                }
            }
            #pragma unroll
            for (int mi = 0; mi < MI; mi++)
                #pragma unroll
                for (int ni = 0; ni < 4; ni++)
                    mma_tf32(d[mi][ni], af[mi][0], af[mi][1], af[mi][2], af[mi][3],
                             bf[ni][0], bf[ni][1]);
        }
        __syncthreads();
    }

    #pragma unroll
    for (int mi = 0; mi < MI; mi++) {
        #pragma unroll
        for (int half = 0; half < 2; half++) {
            const int r = rowBlk + wm * (MI * 16) + mi * 16 + g + half * 8;
            #pragma unroll
            for (int ni = 0; ni < 4; ni++) {
                const int c = colBlk + wn * 32 + ni * 8 + 2 * t;
                float v0 = d[mi][ni][2 * half + 0];
                float v1 = d[mi][ni][2 * half + 1];
                if (MODE == 2) {
                    float2 v = make_float2(v0 * 0.0625f, v1 * 0.0625f);
                    *(float2*)&gP[(size_t)bz * NTOK * NTOK + (size_t)r * NTOK + c] = v;
                } else {
                    const size_t idx = ((size_t)(bz * NTOK + r)) * CC + c;
                    float2 pe = *(const float2*)&gPE[idx];
                    float2 zz = *(const float2*)&gZ[idx];
                    float2 v = make_float2((v0 + pe.x) * zz.x, (v1 + pe.y) * zz.y);
                    *(float2*)&gT[idx] = v;
                }
            }
        }
    }
}

// ---------------- single-pass row softmax (writes tf32-rounded) ----------------
__global__ void __launch_bounds__(256)
softmax_rows(float* __restrict__ P)
{
    float4* row = reinterpret_cast<float4*>(P + (size_t)blockIdx.x * NTOK);
    const int tid = threadIdx.x;
    __shared__ float red[256];

    float4 v[4];
    #pragma unroll
    for (int j = 0; j < 4; j++) v[j] = row[tid + j * 256];

    float m = -3.4e38f;
    #pragma unroll
    for (int j = 0; j < 4; j++)
        m = fmaxf(m, fmaxf(fmaxf(v[j].x, v[j].y), fmaxf(v[j].z, v[j].w)));
    red[tid] = m; __syncthreads();
    for (int s = 128; s > 0; s >>= 1) {
        if (tid < s) red[tid] = fmaxf(red[tid], red[tid + s]);
        __syncthreads();
    }
    m = red[0]; __syncthreads();

    float sum = 0.0f;
    #pragma unroll
    for (int j = 0; j < 4; j++) {
        v[j].x = __expf(v[j].x - m); v[j].y = __expf(v[j].y - m);
        v[j].z = __expf(v[j].z - m); v[j].w = __expf(v[j].w - m);
        sum += v[j].x + v[j].y + v[j].z + v[j].w;
    }
    red[tid] = sum; __syncthreads();
    for (int s = 128; s > 0; s >>= 1) {
        if (tid < s) red[tid] += red[tid + s];
        __syncthreads();
    }
    const float inv = 1.0f / red[0];
    #pragma unroll
    for (int j = 0; j < 4; j++) {
        v[j].x = f2tf32f(v[j].x * inv); v[j].y = f2tf32f(v[j].y * inv);
        v[j].z = f2tf32f(v[j].z * inv); v[j].w = f2tf32f(v[j].w * inv);
        row[tid + j * 256] = v[j];
    }
}

// ---------------- depthwise 3x3 conv PE on q ----------------
__global__ void __launch_bounds__(256)
dwconv_pe(const float* __restrict__ w, const float* __restrict__ bias)
{
    const int idx = blockIdx.x * 256 + threadIdx.x;
    const int c = idx & 255;
    const int n = (idx >> 8) & (NTOK - 1);
    const int b = idx >> 20;
    const int h = n >> 6;
    const int wd = n & 63;

    const float* q = gQ + (size_t)b * NTOK * CC;
    float acc = bias[c];
    #pragma unroll
    for (int di = -1; di <= 1; di++) {
        const int hh = h + di;
        if (hh < 0 || hh > 63) continue;
        #pragma unroll
        for (int dj = -1; dj <= 1; dj++) {
            const int w2 = wd + dj;
            if (w2 < 0 || w2 > 63) continue;
            acc = fmaf(q[(size_t)(hh * 64 + w2) * CC + c],
                       w[c * 9 + (di + 1) * 3 + (dj + 1)], acc);
        }
    }
    gPE[idx] = acc;
}

// ---------------- launch ----------------
extern "C" void kernel_launch(void* const* d_in, const int* in_sizes, int n_in,
                              void* d_out, int out_size)
{
    const float* x     = (const float*)d_in[0];
    const float* Wqkv  = (const float*)d_in[1];
    const float* Wgate = (const float*)d_in[2];
    const float* bgate = (const float*)d_in[3];
    const float* Wproj = (const float*)d_in[4];
    const float* pew   = (const float*)d_in[5];
    const float* peb   = (const float*)d_in[6];
    float* out = (float*)d_out;

    float *pQ, *pK, *pV, *pP, *pT;
    cudaGetSymbolAddress((void**)&pQ, gQ);
    cudaGetSymbolAddress((void**)&pK, gK);
    cudaGetSymbolAddress((void**)&pV, gV);
    cudaGetSymbolAddress((void**)&pP, gP);
    cudaGetSymbolAddress((void**)&pT, gT);

    constexpr int SM0 = (2 * AFL + 2 * BFL0) * 4;         // sync, transpose-B
    constexpr int SM1 = (2 * AFL + 2 * BFL1) * 4;         // sync, direct-B
    constexpr int SMA2 = 3 * (4 * 32 * ASTR + BFL1) * 4;  // async QK: 110592
    constexpr int SMA3 = 3 * (2 * 32 * ASTR + BFL0) * 4;  // async PV: 79872
    cudaFuncSetAttribute(mmagemm<0,0>, cudaFuncAttributeMaxDynamicSharedMemorySize, SM0);
    cudaFuncSetAttribute(mmagemm<1,0>, cudaFuncAttributeMaxDynamicSharedMemorySize, SM0);
    cudaFuncSetAttribute(mmagemm<4,0>, cudaFuncAttributeMaxDynamicSharedMemorySize, SM0);
    cudaFuncSetAttribute(mmagemm_async<2,1,4>, cudaFuncAttributeMaxDynamicSharedMemorySize, SMA2);
    cudaFuncSetAttribute(mmagemm_async<3,0,2>, cudaFuncAttributeMaxDynamicSharedMemorySize, SMA3);

    // 1) qkv = x @ W_qkv -> gQ/gK/gV (tf32-rounded)
    mmagemm<0,0><<<dim3(6,128,1), 256, SM0>>>(x, Wqkv, nullptr, 256, 256, 768, 0, 0, nullptr);
    // 2) z = gelu(x @ W_gate + b)
    mmagemm<1,0><<<dim3(2,128,1), 256, SM0>>>(x, Wgate, nullptr, 256, 256, 256, 0, 0, bgate);
    // 3) PE depthwise conv from gQ
    dwconv_pe<<<dim3(BNTOK * CC / 256), 256>>>(pew, peb);
    // 4) P = scale * Q K^T  (async, pre-rounded operands)
    mmagemm_async<2,1,4><<<dim3(32,32,BB), 256, SMA2>>>(pQ, pK, 256, 256, 256,
                                                        (size_t)NTOK * CC, (size_t)NTOK * CC);
    // 5) softmax rows (writes tf32-rounded P)
    softmax_rows<<<dim3(BB * NTOK), 256>>>(pP);
    // 6) T = (P @ V + PE) * Z  (async, 64-row tiles for balance)
    mmagemm_async<3,0,2><<<dim3(2,64,BB), 256, SMA3>>>(pP, pV, 4096, 4096, 256,
                                                       (size_t)NTOK * NTOK, (size_t)NTOK * CC);
    // 7) out = T @ W_proj
    mmagemm<4,0><<<dim3(2,128,1), 256, SM0>>>(pT, Wproj, out, 256, 256, 256, 0, 0, nullptr);
}

// round 5
// speedup vs baseline: 5.5735x; 1.7486x over previous
#include <cuda_runtime.h>
#include <cuda_fp16.h>
#include <math.h>
#include <stdint.h>

#define BB 4
#define NTOK 4096
#define CC 256
#define BNTOK (BB * NTOK)   // 16384

// ---------------- static scratch ----------------
__device__ float  gQ  [(size_t)BNTOK * CC];          // fp32 Q for dwconv
__device__ __half gQh [(size_t)BNTOK * CC];
__device__ __half gKh [(size_t)BNTOK * CC];
__device__ __half gVh [(size_t)BNTOK * CC];
__device__ float  gZ  [(size_t)BNTOK * CC];
__device__ float  gPE [(size_t)BNTOK * CC];
__device__ __half gTh [(size_t)BNTOK * CC];
__device__ float  gP  [(size_t)BB * NTOK * NTOK];    // 256 MB logits
__device__ __half gPh [(size_t)BB * NTOK * NTOK];    // 128 MB softmaxed P
__device__ __half gXh [(size_t)BNTOK * CC];
__device__ __half gWqkvh[CC * 3 * CC];
__device__ __half gWgateh[CC * CC];
__device__ __half gWprojh[CC * CC];

__device__ __forceinline__ void cpa16(uint32_t dst, const void* src) {
    asm volatile("cp.async.ca.shared.global [%0], [%1], 16;" :: "r"(dst), "l"(src));
}
__device__ __forceinline__ void ldmx4(uint32_t r[4], uint32_t addr) {
    asm volatile("ldmatrix.sync.aligned.m8n8.x4.shared.b16 {%0,%1,%2,%3}, [%4];"
                 : "=r"(r[0]), "=r"(r[1]), "=r"(r[2]), "=r"(r[3]) : "r"(addr));
}
__device__ __forceinline__ void ldmx2(uint32_t r[2], uint32_t addr) {
    asm volatile("ldmatrix.sync.aligned.m8n8.x2.shared.b16 {%0,%1}, [%2];"
                 : "=r"(r[0]), "=r"(r[1]) : "r"(addr));
}
__device__ __forceinline__ void ldmx2t(uint32_t r[2], uint32_t addr) {
    asm volatile("ldmatrix.sync.aligned.m8n8.x2.trans.shared.b16 {%0,%1}, [%2];"
                 : "=r"(r[0]), "=r"(r[1]) : "r"(addr));
}
__device__ __forceinline__ void mma_f16(float d[4], const uint32_t a[4],
                                        uint32_t b0, uint32_t b1) {
    asm volatile(
        "mma.sync.aligned.m16n8k16.row.col.f32.f16.f16.f32 "
        "{%0,%1,%2,%3}, {%4,%5,%6,%7}, {%8,%9}, {%0,%1,%2,%3};"
        : "+f"(d[0]), "+f"(d[1]), "+f"(d[2]), "+f"(d[3])
        : "r"(a[0]), "r"(a[1]), "r"(a[2]), "r"(a[3]), "r"(b0), "r"(b1));
}

// smem geometry (halves): A/B-direct rows stride 40 (80 B), B-trans rows stride 136 (272 B)
#define ASTG 10240                 // bytes per A stage: 128 rows * 80 B
#define BSTG_D 10240               // B direct stage
#define BSTG_T 8704                // B trans stage: 32 rows * 272 B
#define NSTAGE 4

// ======================================================================
// fp16 tensor-core GEMM, cp.async 4-stage, ldmatrix fragments.
// D[m][n] = sum_k A[m][k] * Bop[n][k]
//   TRB=1: B stored [N,K] (K contig)   TRB=0: B stored [K,N] (N contig)
// Tile 128x128, BK=32, 8 warps (2x4), warp tile 64x32.
// MODE 0: qkv split -> gQ(fp32) + gQh/gKh/gVh
// MODE 1: gZ = gelu(acc+bias)
// MODE 2: gP = acc * 0.0625 (fp32)
// MODE 3: gTh = half((acc + gPE) * gZ)
// MODE 4: Out = acc (fp32)
// ======================================================================
template<int MODE, int TRB>
__global__ void __launch_bounds__(256, 2)
hgemm(const __half* __restrict__ A, const __half* __restrict__ B, float* __restrict__ Out,
      int K, int lda, int ldb, size_t sA, size_t sB, const float* __restrict__ bias)
{
    extern __shared__ __align__(16) char sm[];
    constexpr int BSTG = TRB ? BSTG_D : BSTG_T;
    const uint32_t smb = (uint32_t)__cvta_generic_to_shared(sm);
    const uint32_t aBase = smb;
    const uint32_t bBase = smb + NSTAGE * ASTG;

    const int tid  = threadIdx.x;
    const int wid  = tid >> 5;
    const int lane = tid & 31;
    const int g    = lane >> 2;
    const int t    = lane & 3;
    const int wm   = wid >> 2;
    const int wn   = wid & 3;

    const int bz     = blockIdx.z;
    const int rowBlk = blockIdx.y * 128;
    const int colBlk = blockIdx.x * 128;
    const __half* Ab = A + (size_t)bz * sA;
    const __half* Bb = B + (size_t)bz * sB;
    const int NC = K >> 5;

    float d[4][4][4];
    #pragma unroll
    for (int mi = 0; mi < 4; mi++)
        #pragma unroll
        for (int ni = 0; ni < 4; ni++)
            #pragma unroll
            for (int j = 0; j < 4; j++) d[mi][ni][j] = 0.0f;

    auto loadStage = [&](int c) {
        const int kt = c << 5;
        const int sb = c & (NSTAGE - 1);
        const uint32_t aS = aBase + sb * ASTG;
        #pragma unroll
        for (int j = 0; j < 2; j++) {
            const int task = tid + j * 256;           // 512 tasks: 128 rows x 4 chunks
            const int row = task >> 2, ch = task & 3;
            cpa16(aS + row * 80 + ch * 16,
                  Ab + (size_t)(rowBlk + row) * lda + kt + ch * 8);
        }
        const uint32_t bS = bBase + sb * BSTG;
        if (TRB) {
            #pragma unroll
            for (int j = 0; j < 2; j++) {
                const int task = tid + j * 256;
                const int row = task >> 2, ch = task & 3;
                cpa16(bS + row * 80 + ch * 16,
                      Bb + (size_t)(colBlk + row) * ldb + kt + ch * 8);
            }
        } else {
            #pragma unroll
            for (int j = 0; j < 2; j++) {
                const int task = tid + j * 256;       // 32 rows x 16 chunks
                const int row = task >> 4, ch = task & 15;
                cpa16(bS + row * 272 + ch * 16,
                      Bb + (size_t)(kt + row) * ldb + colBlk + ch * 8);
            }
        }
        asm volatile("cp.async.commit_group;");
    };

    loadStage(0); loadStage(1); loadStage(2);

    for (int c = 0; c < NC; ++c) {
        asm volatile("cp.async.wait_group 2;");
        __syncthreads();
        if (c + 3 < NC) loadStage(c + 3);

        const int sb = c & (NSTAGE - 1);
        const uint32_t aS = aBase + sb * ASTG;
        const uint32_t bS = bBase + sb * BSTG;

        #pragma unroll
        for (int s = 0; s < 2; s++) {
            const int k0 = 16 * s;
            uint32_t a[4][4];
            #pragma unroll
            for (int mi = 0; mi < 4; mi++) {
                const int r0 = wm * 64 + mi * 16;
                ldmx4(a[mi], aS + ((r0 + (lane & 15)) * 40 + k0 + (lane >> 4) * 8) * 2);
            }
            uint32_t b[4][2];
            #pragma unroll
            for (int ni = 0; ni < 4; ni++) {
                const int n0 = wn * 32 + ni * 8;
                if (TRB)
                    ldmx2(b[ni], bS + ((n0 + (lane & 7)) * 40 + k0 + ((lane >> 3) & 1) * 8) * 2);
                else
                    ldmx2t(b[ni], bS + ((k0 + (lane & 15)) * 136 + n0) * 2);
            }
            #pragma unroll
            for (int mi = 0; mi < 4; mi++)
                #pragma unroll
                for (int ni = 0; ni < 4; ni++)
                    mma_f16(d[mi][ni], a[mi], b[ni][0], b[ni][1]);
        }
        __syncthreads();
    }

    // ---- epilogue ----
    #pragma unroll
    for (int mi = 0; mi < 4; mi++) {
        #pragma unroll
        for (int half = 0; half < 2; half++) {
            const int r = rowBlk + wm * 64 + mi * 16 + g + half * 8;
            #pragma unroll
            for (int ni = 0; ni < 4; ni++) {
                const int c = colBlk + wn * 32 + ni * 8 + 2 * t;
                float v0 = d[mi][ni][2 * half + 0];
                float v1 = d[mi][ni][2 * half + 1];

                if (MODE == 2) {
                    *(float2*)&gP[(size_t)bz * NTOK * NTOK + (size_t)r * NTOK + c] =
                        make_float2(v0 * 0.0625f, v1 * 0.0625f);
                } else if (MODE == 3) {
                    const size_t idx = ((size_t)(bz * NTOK + r)) * CC + c;
                    float2 pe = *(const float2*)&gPE[idx];
                    float2 zz = *(const float2*)&gZ[idx];
                    *(__half2*)&gTh[idx] =
                        __floats2half2_rn((v0 + pe.x) * zz.x, (v1 + pe.y) * zz.y);
                } else if (MODE == 0) {
                    const int seg = c >> 8;
                    const int cc = c & 255;
                    const size_t idx = (size_t)r * CC + cc;
                    __half2 hv = __floats2half2_rn(v0, v1);
                    if (seg == 0) {
                        *(float2*)&gQ[idx] = make_float2(v0, v1);
                        *(__half2*)&gQh[idx] = hv;
                    } else if (seg == 1) {
                        *(__half2*)&gKh[idx] = hv;
                    } else {
                        *(__half2*)&gVh[idx] = hv;
                    }
                } else if (MODE == 1) {
                    float2 bb = *(const float2*)&bias[c];
                    float a0 = v0 + bb.x, a1 = v1 + bb.y;
                    float2 v;
                    v.x = 0.5f * a0 * (1.0f + erff(a0 * 0.70710678118654752f));
                    v.y = 0.5f * a1 * (1.0f + erff(a1 * 0.70710678118654752f));
                    *(float2*)&gZ[(size_t)r * CC + c] = v;
                } else {
                    *(float2*)&Out[(size_t)r * CC + c] = make_float2(v0, v1);
                }
            }
        }
    }
}

// ---------------- fp32 -> fp16 convert ----------------
__global__ void __launch_bounds__(256)
f2h(const float* __restrict__ src, __half* __restrict__ dst, int n2)
{
    int i = blockIdx.x * 256 + threadIdx.x;
    if (i < n2) {
        float2 v = *(const float2*)(src + 2 * i);
        *(__half2*)(dst + 2 * i) = __floats2half2_rn(v.x, v.y);
    }
}

// ---------------- single-pass row softmax: fp32 in, fp16 out ----------------
__global__ void __launch_bounds__(256)
softmax_rows(const float* __restrict__ P, __half* __restrict__ Ph)
{
    const float4* row = reinterpret_cast<const float4*>(P + (size_t)blockIdx.x * NTOK);
    __half2* rowh = reinterpret_cast<__half2*>(Ph + (size_t)blockIdx.x * NTOK);
    const int tid = threadIdx.x;
    __shared__ float red[256];

    float4 v[4];
    #pragma unroll
    for (int j = 0; j < 4; j++) v[j] = row[tid + j * 256];

    float m = -3.4e38f;
    #pragma unroll
    for (int j = 0; j < 4; j++)
        m = fmaxf(m, fmaxf(fmaxf(v[j].x, v[j].y), fmaxf(v[j].z, v[j].w)));
    red[tid] = m; __syncthreads();
    for (int s = 128; s > 0; s >>= 1) {
        if (tid < s) red[tid] = fmaxf(red[tid], red[tid + s]);
        __syncthreads();
    }
    m = red[0]; __syncthreads();

    float sum = 0.0f;
    #pragma unroll
    for (int j = 0; j < 4; j++) {
        v[j].x = __expf(v[j].x - m); v[j].y = __expf(v[j].y - m);
        v[j].z = __expf(v[j].z - m); v[j].w = __expf(v[j].w - m);
        sum += v[j].x + v[j].y + v[j].z + v[j].w;
    }
    red[tid] = sum; __syncthreads();
    for (int s = 128; s > 0; s >>= 1) {
        if (tid < s) red[tid] += red[tid + s];
        __syncthreads();
    }
    const float inv = 1.0f / red[0];
    #pragma unroll
    for (int j = 0; j < 4; j++) {
        rowh[2 * (tid + j * 256) + 0] = __floats2half2_rn(v[j].x * inv, v[j].y * inv);
        rowh[2 * (tid + j * 256) + 1] = __floats2half2_rn(v[j].z * inv, v[j].w * inv);
    }
}

// ---------------- depthwise 3x3 conv PE on q ----------------
__global__ void __launch_bounds__(256)
dwconv_pe(const float* __restrict__ w, const float* __restrict__ bias)
{
    const int idx = blockIdx.x * 256 + threadIdx.x;
    const int c = idx & 255;
    const int n = (idx >> 8) & (NTOK - 1);
    const int b = idx >> 20;
    const int h = n >> 6;
    const int wd = n & 63;

    const float* q = gQ + (size_t)b * NTOK * CC;
    float acc = bias[c];
    #pragma unroll
    for (int di = -1; di <= 1; di++) {
        const int hh = h + di;
        if (hh < 0 || hh > 63) continue;
        #pragma unroll
        for (int dj = -1; dj <= 1; dj++) {
            const int w2 = wd + dj;
            if (w2 < 0 || w2 > 63) continue;
            acc = fmaf(q[(size_t)(hh * 64 + w2) * CC + c],
                       w[c * 9 + (di + 1) * 3 + (dj + 1)], acc);
        }
    }
    gPE[idx] = acc;
}

// ---------------- launch ----------------
extern "C" void kernel_launch(void* const* d_in, const int* in_sizes, int n_in,
                              void* d_out, int out_size)
{
    const float* x     = (const float*)d_in[0];
    const float* Wqkv  = (const float*)d_in[1];
    const float* Wgate = (const float*)d_in[2];
    const float* bgate = (const float*)d_in[3];
    const float* Wproj = (const float*)d_in[4];
    const float* pew   = (const float*)d_in[5];
    const float* peb   = (const float*)d_in[6];
    float* out = (float*)d_out;

    __half *pXh, *pWqkvh, *pWgateh, *pWprojh, *pQh, *pKh, *pVh, *pPh, *pTh;
    float *pP;
    cudaGetSymbolAddress((void**)&pXh, gXh);
    cudaGetSymbolAddress((void**)&pWqkvh, gWqkvh);
    cudaGetSymbolAddress((void**)&pWgateh, gWgateh);
    cudaGetSymbolAddress((void**)&pWprojh, gWprojh);
    cudaGetSymbolAddress((void**)&pQh, gQh);
    cudaGetSymbolAddress((void**)&pKh, gKh);
    cudaGetSymbolAddress((void**)&pVh, gVh);
    cudaGetSymbolAddress((void**)&pPh, gPh);
    cudaGetSymbolAddress((void**)&pTh, gTh);
    cudaGetSymbolAddress((void**)&pP, gP);

    constexpr int SMD = NSTAGE * (ASTG + BSTG_D);   // 81920 (direct-B)
    constexpr int SMT = NSTAGE * (ASTG + BSTG_T);   // 75776 (trans-B)
    cudaFuncSetAttribute(hgemm<0,0>, cudaFuncAttributeMaxDynamicSharedMemorySize, SMT);
    cudaFuncSetAttribute(hgemm<1,0>, cudaFuncAttributeMaxDynamicSharedMemorySize, SMT);
    cudaFuncSetAttribute(hgemm<2,1>, cudaFuncAttributeMaxDynamicSharedMemorySize, SMD);
    cudaFuncSetAttribute(hgemm<3,0>, cudaFuncAttributeMaxDynamicSharedMemorySize, SMT);
    cudaFuncSetAttribute(hgemm<4,0>, cudaFuncAttributeMaxDynamicSharedMemorySize, SMT);

    // 0) fp16 conversions
    f2h<<<dim3(BNTOK * CC / 512), 256>>>(x, pXh, BNTOK * CC / 2);
    f2h<<<dim3(CC * 3 * CC / 512), 256>>>(Wqkv, pWqkvh, CC * 3 * CC / 2);
    f2h<<<dim3(CC * CC / 512), 256>>>(Wgate, pWgateh, CC * CC / 2);
    f2h<<<dim3(CC * CC / 512), 256>>>(Wproj, pWprojh, CC * CC / 2);

    // 1) qkv = x @ W_qkv -> gQ(fp32) + gQh/gKh/gVh
    hgemm<0,0><<<dim3(6,128,1), 256, SMT>>>(pXh, pWqkvh, nullptr, 256, 256, 768, 0, 0, nullptr);
    // 2) z = gelu(x @ W_gate + b)
    hgemm<1,0><<<dim3(2,128,1), 256, SMT>>>(pXh, pWgateh, nullptr, 256, 256, 256, 0, 0, bgate);
    // 3) PE depthwise conv from gQ
    dwconv_pe<<<dim3(BNTOK * CC / 256), 256>>>(pew, peb);
    // 4) P = scale * Q K^T
    hgemm<2,1><<<dim3(32,32,BB), 256, SMD>>>(pQh, pKh, nullptr, 256, 256, 256,
                                             (size_t)NTOK * CC, (size_t)NTOK * CC, nullptr);
    // 5) softmax rows -> fp16 P
    softmax_rows<<<dim3(BB * NTOK), 256>>>(pP, pPh);
    // 6) T = (P @ V + PE) * Z -> gTh
    hgemm<3,0><<<dim3(2,32,BB), 256, SMT>>>(pPh, pVh, nullptr, 4096, 4096, 256,
                                            (size_t)NTOK * NTOK, (size_t)NTOK * CC, nullptr);
    // 7) out = T @ W_proj
    hgemm<4,0><<<dim3(2,128,1), 256, SMT>>>(pTh, pWprojh, out, 256, 256, 256, 0, 0, nullptr);
}

// round 6
// speedup vs baseline: 6.4297x; 1.1536x over previous
#include <cuda_runtime.h>
#include <cuda_fp16.h>
#include <math.h>
#include <stdint.h>

#define BB 4
#define NTOK 4096
#define CC 256
#define BNTOK (BB * NTOK)   // 16384

// ---------------- static scratch ----------------
__device__ float  gQ  [(size_t)BNTOK * CC];          // fp32 Q for dwconv
__device__ __half gQh [(size_t)BNTOK * CC];
__device__ __half gKh [(size_t)BNTOK * CC];
__device__ __half gVh [(size_t)BNTOK * CC];
__device__ float  gZ  [(size_t)BNTOK * CC];
__device__ float  gPE [(size_t)BNTOK * CC];
__device__ __half gTh [(size_t)BNTOK * CC];
__device__ __half gPh [(size_t)BB * NTOK * NTOK];    // 128 MB: E = exp(scaled logits)
__device__ float  gL  [BNTOK];                       // row sums of E
__device__ __half gXh [(size_t)BNTOK * CC];
__device__ __half gWqkvh[CC * 3 * CC];
__device__ __half gWgateh[CC * CC];
__device__ __half gWprojh[CC * CC];

__device__ __forceinline__ void cpa16(uint32_t dst, const void* src) {
    asm volatile("cp.async.ca.shared.global [%0], [%1], 16;" :: "r"(dst), "l"(src));
}
__device__ __forceinline__ void ldmx4(uint32_t r[4], uint32_t addr) {
    asm volatile("ldmatrix.sync.aligned.m8n8.x4.shared.b16 {%0,%1,%2,%3}, [%4];"
                 : "=r"(r[0]), "=r"(r[1]), "=r"(r[2]), "=r"(r[3]) : "r"(addr));
}
__device__ __forceinline__ void ldmx2(uint32_t r[2], uint32_t addr) {
    asm volatile("ldmatrix.sync.aligned.m8n8.x2.shared.b16 {%0,%1}, [%2];"
                 : "=r"(r[0]), "=r"(r[1]) : "r"(addr));
}
__device__ __forceinline__ void ldmx2t(uint32_t r[2], uint32_t addr) {
    asm volatile("ldmatrix.sync.aligned.m8n8.x2.trans.shared.b16 {%0,%1}, [%2];"
                 : "=r"(r[0]), "=r"(r[1]) : "r"(addr));
}
__device__ __forceinline__ void mma_f16(float d[4], const uint32_t a[4],
                                        uint32_t b0, uint32_t b1) {
    asm volatile(
        "mma.sync.aligned.m16n8k16.row.col.f32.f16.f16.f32 "
        "{%0,%1,%2,%3}, {%4,%5,%6,%7}, {%8,%9}, {%0,%1,%2,%3};"
        : "+f"(d[0]), "+f"(d[1]), "+f"(d[2]), "+f"(d[3])
        : "r"(a[0]), "r"(a[1]), "r"(a[2]), "r"(a[3]), "r"(b0), "r"(b1));
}

#define ASTG 10240                 // bytes per A stage: 128 rows * 80 B
#define BSTG_D 10240               // B direct stage
#define BSTG_T 8704                // B trans stage: 32 rows * 272 B
#define NSTAGE 4

// ======================================================================
// fp16 tensor-core GEMM, cp.async 4-stage, ldmatrix fragments.
// D[m][n] = sum_k A[m][k] * Bop[n][k]
//   TRB=1: B stored [N,K] (K contig)   TRB=0: B stored [K,N] (N contig)
// Tile 128x128, BK=32, 8 warps (2x4), warp tile 64x32.
// MODE 0: qkv split -> gQ(fp32) + gQh/gKh/gVh
// MODE 1: gZ = gelu(acc+bias)
// MODE 2: gPh = half(exp(acc*0.0625)); gL[row] += rowsum (unnormalized softmax)
// MODE 3: gTh/out path: Out = (acc/L + gPE) * gZ   (fp32 out)
// MODE 4: Out = acc (fp32)
// ======================================================================
template<int MODE, int TRB>
__global__ void __launch_bounds__(256, 2)
hgemm(const __half* __restrict__ A, const __half* __restrict__ B, float* __restrict__ Out,
      int K, int lda, int ldb, size_t sA, size_t sB, const float* __restrict__ bias)
{
    extern __shared__ __align__(16) char sm[];
    constexpr int BSTG = TRB ? BSTG_D : BSTG_T;
    const uint32_t smb = (uint32_t)__cvta_generic_to_shared(sm);
    const uint32_t aBase = smb;
    const uint32_t bBase = smb + NSTAGE * ASTG;

    const int tid  = threadIdx.x;
    const int wid  = tid >> 5;
    const int lane = tid & 31;
    const int g    = lane >> 2;
    const int t    = lane & 3;
    const int wm   = wid >> 2;
    const int wn   = wid & 3;

    const int bz     = blockIdx.z;
    const int rowBlk = blockIdx.y * 128;
    const int colBlk = blockIdx.x * 128;
    const __half* Ab = A + (size_t)bz * sA;
    const __half* Bb = B + (size_t)bz * sB;
    const int NC = K >> 5;

    float d[4][4][4];
    #pragma unroll
    for (int mi = 0; mi < 4; mi++)
        #pragma unroll
        for (int ni = 0; ni < 4; ni++)
            #pragma unroll
            for (int j = 0; j < 4; j++) d[mi][ni][j] = 0.0f;

    auto loadStage = [&](int c) {
        const int kt = c << 5;
        const int sb = c & (NSTAGE - 1);
        const uint32_t aS = aBase + sb * ASTG;
        #pragma unroll
        for (int j = 0; j < 2; j++) {
            const int task = tid + j * 256;           // 512 tasks: 128 rows x 4 chunks
            const int row = task >> 2, ch = task & 3;
            cpa16(aS + row * 80 + ch * 16,
                  Ab + (size_t)(rowBlk + row) * lda + kt + ch * 8);
        }
        const uint32_t bS = bBase + sb * BSTG;
        if (TRB) {
            #pragma unroll
            for (int j = 0; j < 2; j++) {
                const int task = tid + j * 256;
                const int row = task >> 2, ch = task & 3;
                cpa16(bS + row * 80 + ch * 16,
                      Bb + (size_t)(colBlk + row) * ldb + kt + ch * 8);
            }
        } else {
            #pragma unroll
            for (int j = 0; j < 2; j++) {
                const int task = tid + j * 256;       // 32 rows x 16 chunks
                const int row = task >> 4, ch = task & 15;
                cpa16(bS + row * 272 + ch * 16,
                      Bb + (size_t)(kt + row) * ldb + colBlk + ch * 8);
            }
        }
        asm volatile("cp.async.commit_group;");
    };

    loadStage(0); loadStage(1); loadStage(2);

    for (int c = 0; c < NC; ++c) {
        asm volatile("cp.async.wait_group 2;");
        __syncthreads();
        if (c + 3 < NC) loadStage(c + 3);

        const int sb = c & (NSTAGE - 1);
        const uint32_t aS = aBase + sb * ASTG;
        const uint32_t bS = bBase + sb * BSTG;

        #pragma unroll
        for (int s = 0; s < 2; s++) {
            const int k0 = 16 * s;
            uint32_t a[4][4];
            #pragma unroll
            for (int mi = 0; mi < 4; mi++) {
                const int r0 = wm * 64 + mi * 16;
                ldmx4(a[mi], aS + ((r0 + (lane & 15)) * 40 + k0 + (lane >> 4) * 8) * 2);
            }
            uint32_t b[4][2];
            #pragma unroll
            for (int ni = 0; ni < 4; ni++) {
                const int n0 = wn * 32 + ni * 8;
                if (TRB)
                    ldmx2(b[ni], bS + ((n0 + (lane & 7)) * 40 + k0 + ((lane >> 3) & 1) * 8) * 2);
                else
                    ldmx2t(b[ni], bS + ((k0 + (lane & 15)) * 136 + n0) * 2);
            }
            #pragma unroll
            for (int mi = 0; mi < 4; mi++)
                #pragma unroll
                for (int ni = 0; ni < 4; ni++)
                    mma_f16(d[mi][ni], a[mi], b[ni][0], b[ni][1]);
        }
        __syncthreads();
    }

    // ---- epilogue ----
    #pragma unroll
    for (int mi = 0; mi < 4; mi++) {
        #pragma unroll
        for (int half = 0; half < 2; half++) {
            const int r = rowBlk + wm * 64 + mi * 16 + g + half * 8;

            if (MODE == 2) {
                // E = exp(scaled logits), fp16 store, fp32 rowsum via atomics.
                float rsum = 0.0f;
                #pragma unroll
                for (int ni = 0; ni < 4; ni++) {
                    const int c = colBlk + wn * 32 + ni * 8 + 2 * t;
                    float e0 = __expf(d[mi][ni][2 * half + 0] * 0.0625f);
                    float e1 = __expf(d[mi][ni][2 * half + 1] * 0.0625f);
                    __half2 hv = __floats2half2_rn(e0, e1);
                    *(__half2*)&gPh[(size_t)bz * NTOK * NTOK + (size_t)r * NTOK + c] = hv;
                    rsum += __low2float(hv) + __high2float(hv);
                }
                rsum += __shfl_xor_sync(0xffffffffu, rsum, 1);
                rsum += __shfl_xor_sync(0xffffffffu, rsum, 2);
                if (t == 0) atomicAdd(&gL[bz * NTOK + r], rsum);
                continue;
            }

            float invL = 1.0f;
            if (MODE == 3) invL = 1.0f / gL[bz * NTOK + r];

            #pragma unroll
            for (int ni = 0; ni < 4; ni++) {
                const int c = colBlk + wn * 32 + ni * 8 + 2 * t;
                float v0 = d[mi][ni][2 * half + 0];
                float v1 = d[mi][ni][2 * half + 1];

                if (MODE == 3) {
                    const size_t idx = ((size_t)(bz * NTOK + r)) * CC + c;
                    float2 pe = *(const float2*)&gPE[idx];
                    float2 zz = *(const float2*)&gZ[idx];
                    *(__half2*)&gTh[idx] =
                        __floats2half2_rn((v0 * invL + pe.x) * zz.x,
                                          (v1 * invL + pe.y) * zz.y);
                } else if (MODE == 0) {
                    const int seg = c >> 8;
                    const int cc = c & 255;
                    const size_t idx = (size_t)r * CC + cc;
                    __half2 hv = __floats2half2_rn(v0, v1);
                    if (seg == 0) {
                        *(float2*)&gQ[idx] = make_float2(v0, v1);
                        *(__half2*)&gQh[idx] = hv;
                    } else if (seg == 1) {
                        *(__half2*)&gKh[idx] = hv;
                    } else {
                        *(__half2*)&gVh[idx] = hv;
                    }
                } else if (MODE == 1) {
                    float2 bb = *(const float2*)&bias[c];
                    float a0 = v0 + bb.x, a1 = v1 + bb.y;
                    float2 v;
                    v.x = 0.5f * a0 * (1.0f + erff(a0 * 0.70710678118654752f));
                    v.y = 0.5f * a1 * (1.0f + erff(a1 * 0.70710678118654752f));
                    *(float2*)&gZ[(size_t)r * CC + c] = v;
                } else {
                    *(float2*)&Out[(size_t)r * CC + c] = make_float2(v0, v1);
                }
            }
        }
    }
}

// ---------------- fused convert (x + 3 weights -> fp16) + zero gL ----------------
#define N2_X   (BNTOK * CC / 2)        // 2097152
#define N2_QKV (CC * 3 * CC / 2)       // 98304
#define N2_GW  (CC * CC / 2)           // 32768
__global__ void __launch_bounds__(256)
convert_all(const float* __restrict__ x, const float* __restrict__ Wqkv,
            const float* __restrict__ Wgate, const float* __restrict__ Wproj)
{
    int i = blockIdx.x * 256 + threadIdx.x;
    if (i < BNTOK) gL[i] = 0.0f;

    const float* src; __half* dst; int off;
    if (i < N2_X)                        { src = x;     dst = gXh;    off = i; }
    else if ((i -= N2_X) < N2_QKV)       { src = Wqkv;  dst = gWqkvh; off = i; }
    else if ((i -= N2_QKV) < N2_GW)      { src = Wgate; dst = gWgateh; off = i; }
    else if ((i -= N2_GW) < N2_GW)       { src = Wproj; dst = gWprojh; off = i; }
    else return;
    float2 v = *(const float2*)(src + 2 * off);
    *(__half2*)(dst + 2 * off) = __floats2half2_rn(v.x, v.y);
}

// ---------------- depthwise 3x3 conv PE on q ----------------
__global__ void __launch_bounds__(256)
dwconv_pe(const float* __restrict__ w, const float* __restrict__ bias)
{
    const int idx = blockIdx.x * 256 + threadIdx.x;
    const int c = idx & 255;
    const int n = (idx >> 8) & (NTOK - 1);
    const int b = idx >> 20;
    const int h = n >> 6;
    const int wd = n & 63;

    const float* q = gQ + (size_t)b * NTOK * CC;
    float acc = bias[c];
    #pragma unroll
    for (int di = -1; di <= 1; di++) {
        const int hh = h + di;
        if (hh < 0 || hh > 63) continue;
        #pragma unroll
        for (int dj = -1; dj <= 1; dj++) {
            const int w2 = wd + dj;
            if (w2 < 0 || w2 > 63) continue;
            acc = fmaf(q[(size_t)(hh * 64 + w2) * CC + c],
                       w[c * 9 + (di + 1) * 3 + (dj + 1)], acc);
        }
    }
    gPE[idx] = acc;
}

// ---------------- launch ----------------
extern "C" void kernel_launch(void* const* d_in, const int* in_sizes, int n_in,
                              void* d_out, int out_size)
{
    const float* x     = (const float*)d_in[0];
    const float* Wqkv  = (const float*)d_in[1];
    const float* Wgate = (const float*)d_in[2];
    const float* bgate = (const float*)d_in[3];
    const float* Wproj = (const float*)d_in[4];
    const float* pew   = (const float*)d_in[5];
    const float* peb   = (const float*)d_in[6];
    float* out = (float*)d_out;

    __half *pXh, *pWqkvh, *pWgateh, *pWprojh, *pQh, *pKh, *pVh, *pPh, *pTh;
    cudaGetSymbolAddress((void**)&pXh, gXh);
    cudaGetSymbolAddress((void**)&pWqkvh, gWqkvh);
    cudaGetSymbolAddress((void**)&pWgateh, gWgateh);
    cudaGetSymbolAddress((void**)&pWprojh, gWprojh);
    cudaGetSymbolAddress((void**)&pQh, gQh);
    cudaGetSymbolAddress((void**)&pKh, gKh);
    cudaGetSymbolAddress((void**)&pVh, gVh);
    cudaGetSymbolAddress((void**)&pPh, gPh);
    cudaGetSymbolAddress((void**)&pTh, gTh);

    constexpr int SMD = NSTAGE * (ASTG + BSTG_D);   // 81920 (direct-B)
    constexpr int SMT = NSTAGE * (ASTG + BSTG_T);   // 75776 (trans-B)
    cudaFuncSetAttribute(hgemm<0,0>, cudaFuncAttributeMaxDynamicSharedMemorySize, SMT);
    cudaFuncSetAttribute(hgemm<1,0>, cudaFuncAttributeMaxDynamicSharedMemorySize, SMT);
    cudaFuncSetAttribute(hgemm<2,1>, cudaFuncAttributeMaxDynamicSharedMemorySize, SMD);
    cudaFuncSetAttribute(hgemm<3,0>, cudaFuncAttributeMaxDynamicSharedMemorySize, SMT);
    cudaFuncSetAttribute(hgemm<4,0>, cudaFuncAttributeMaxDynamicSharedMemorySize, SMT);

    // 0) converts + zero row sums
    const int cvt_n = N2_X + N2_QKV + 2 * N2_GW;
    convert_all<<<dim3((cvt_n + 255) / 256), 256>>>(x, Wqkv, Wgate, Wproj);

    // 1) qkv = x @ W_qkv -> gQ(fp32) + gQh/gKh/gVh
    hgemm<0,0><<<dim3(6,128,1), 256, SMT>>>(pXh, pWqkvh, nullptr, 256, 256, 768, 0, 0, nullptr);
    // 2) z = gelu(x @ W_gate + b)
    hgemm<1,0><<<dim3(2,128,1), 256, SMT>>>(pXh, pWgateh, nullptr, 256, 256, 256, 0, 0, bgate);
    // 3) PE depthwise conv from gQ
    dwconv_pe<<<dim3(BNTOK * CC / 256), 256>>>(pew, peb);
    // 4) E = exp(scale * Q K^T), row sums into gL (fused, unnormalized softmax)
    hgemm<2,1><<<dim3(32,32,BB), 256, SMD>>>(pQh, pKh, nullptr, 256, 256, 256,
                                             (size_t)NTOK * CC, (size_t)NTOK * CC, nullptr);
    // 5) T = (E @ V / L + PE) * Z -> gTh
    hgemm<3,0><<<dim3(2,32,BB), 256, SMT>>>(pPh, pVh, nullptr, 4096, 4096, 256,
                                            (size_t)NTOK * NTOK, (size_t)NTOK * CC, nullptr);
    // 6) out = T @ W_proj
    hgemm<4,0><<<dim3(2,128,1), 256, SMT>>>(pTh, pWprojh, out, 256, 256, 256, 0, 0, nullptr);
}